// round 14
// baseline (speedup 1.0000x reference)
#include <cuda_runtime.h>
#include <math.h>
#include <stdint.h>

// Problem constants
#define B_   2
#define N_   3072
#define D_   320
#define H_   8
#define DH_  40
#define BH_  16
#define SCALE_ 0.15811388300841898f   // 40^-0.5
#define SPLIT 2

// ---------------- scratch (no allocation allowed) ----------------
__device__ float g_Q[BH_ * N_ * DH_];   // [bh, n, dh], pre-scaled, tf32-rounded
__device__ float g_K[BH_ * N_ * DH_];   // tf32-rounded
__device__ float g_V[BH_ * N_ * DH_];   // tf32-rounded
__device__ float g_O[B_ * N_ * D_];     // attention output, [b, n, h*40+c]
__device__ float g_Po[SPLIT * BH_ * N_ * DH_];  // unnormalized partial O
__device__ float g_Pl[SPLIT * BH_ * N_];        // partial row sums
__device__ unsigned char g_M1[B_ * N_];
__device__ unsigned char g_M2[B_ * N_];

// ---------------- helpers ----------------
__device__ __forceinline__ float f2tf32(float x) {
    uint32_t u;
    asm("cvt.rna.tf32.f32 %0, %1;" : "=r"(u) : "f"(x));
    return __uint_as_float(u);
}

__device__ __forceinline__ void mma_tf32(
    float& d0, float& d1, float& d2, float& d3,
    float a0, float a1, float a2, float a3,
    float b0, float b1)
{
    asm volatile(
        "mma.sync.aligned.m16n8k8.row.col.f32.tf32.tf32.f32 "
        "{%0,%1,%2,%3}, {%4,%5,%6,%7}, {%8,%9}, {%0,%1,%2,%3};"
        : "+f"(d0), "+f"(d1), "+f"(d2), "+f"(d3)
        : "r"(__float_as_uint(a0)), "r"(__float_as_uint(a1)),
          "r"(__float_as_uint(a2)), "r"(__float_as_uint(a3)),
          "r"(__float_as_uint(b0)), "r"(__float_as_uint(b1)));
}

__device__ __forceinline__ void cpa16(uint32_t dst, const void* src) {
    asm volatile("cp.async.ca.shared.global [%0], [%1], 16;" :: "r"(dst), "l"(src));
}

// ---------------- mask kernel ----------------
__global__ void mask_kernel(const float* __restrict__ mask1,
                            const float* __restrict__ mask2) {
    int idx = blockIdx.x * 256 + threadIdx.x;
    if (idx >= B_ * N_) return;
    int b = idx / N_, i = idx - b * N_;
    int y = i / 48, x = i - y * 48;
    size_t src = ((size_t)b * 512 + (size_t)y * 8) * 384 + (size_t)x * 8;
    g_M1[idx] = (mask1[src] >= 0.5f) ? 1 : 0;
    g_M2[idx] = (mask2[src] >= 0.5f) ? 1 : 0;
}

// ---------------- tf32 tensor-core GEMM (R10 known-good form) --------------
// mode 0: QKV fused (blockIdx.z = 0/1/2 -> Q/K/V), scatter + tf32 round
// mode 3: A = g_O, dst = acc + bias
#define TBM 64
#define TBN 64
#define TBK 16
#define ASL 20      // As [m][k] stride: banks (20g+t) mod 32 all distinct
#define WSL 72      // Ws [k][n] stride: banks (8t+g)  mod 32 all distinct
#define NKT (D_ / TBK)   // 20 k-tiles

__global__ __launch_bounds__(128) void gemm_tf32_kernel(
    const float* __restrict__ x, const float* __restrict__ ctx,
    const float* __restrict__ Wq, const float* __restrict__ Wk,
    const float* __restrict__ Wv, const float* __restrict__ bias,
    int mode, float* __restrict__ dst)
{
    __shared__ float As[2][TBM * ASL];
    __shared__ float Ws[2][TBK * WSL];

    const int z = blockIdx.z;
    const float* Ain;
    const float* W;
    float scale;
    if (mode == 3) { Ain = (const float*)g_O; W = Wq; scale = 1.f; }
    else {
        Ain = (z == 0) ? x : ctx;
        W = (z == 0) ? Wq : (z == 1) ? Wk : Wv;
        scale = (z == 0) ? SCALE_ : 1.f;
    }

    const int bm = blockIdx.y * TBM;
    const int bn = blockIdx.x * TBN;
    const int tid = threadIdx.x;
    const int w = tid >> 5, lane = tid & 31;
    const int g = lane >> 2, t = lane & 3;
    const int wm = (w & 1) * 32;
    const int wn = (w >> 1) * 32;

    float acc[2][4][4];
    #pragma unroll
    for (int mi = 0; mi < 2; mi++)
        #pragma unroll
        for (int ni = 0; ni < 4; ni++)
            #pragma unroll
            for (int r = 0; r < 4; r++) acc[mi][ni][r] = 0.f;

    auto issue = [&](int k0, int bufi) {
        uint32_t abase = (uint32_t)__cvta_generic_to_shared(&As[bufi][0]);
        uint32_t wbase = (uint32_t)__cvta_generic_to_shared(&Ws[bufi][0]);
        #pragma unroll
        for (int i = 0; i < 2; i++) {
            int ch = tid * 2 + i;
            int r = ch >> 2, c = (ch & 3) * 4;
            cpa16(abase + (uint32_t)(r * ASL + c) * 4,
                  Ain + (size_t)(bm + r) * D_ + k0 + c);
        }
        #pragma unroll
        for (int i = 0; i < 2; i++) {
            int ch = tid * 2 + i;
            int r = ch >> 4, c = (ch & 15) * 4;
            cpa16(wbase + (uint32_t)(r * WSL + c) * 4,
                  W + (size_t)(k0 + r) * D_ + bn + c);
        }
    };

    issue(0, 0);
    asm volatile("cp.async.commit_group;");

    for (int kt = 0; kt < NKT; kt++) {
        int buf = kt & 1;
        if (kt + 1 < NKT) {
            issue((kt + 1) * TBK, buf ^ 1);
            asm volatile("cp.async.commit_group;");
            asm volatile("cp.async.wait_group 1;");
        } else {
            asm volatile("cp.async.wait_group 0;");
        }
        __syncthreads();

        const float* Ab = &As[buf][0];
        const float* Wb = &Ws[buf][0];

        #pragma unroll
        for (int kk = 0; kk < 2; kk++) {
            const int kb = kk * 8;
            float a[2][4];
            #pragma unroll
            for (int mi = 0; mi < 2; mi++) {
                const float* ar0 = Ab + (wm + mi * 16 + g) * ASL + kb;
                const float* ar1 = Ab + (wm + mi * 16 + g + 8) * ASL + kb;
                a[mi][0] = f2tf32(ar0[t]);
                a[mi][1] = f2tf32(ar1[t]);
                a[mi][2] = f2tf32(ar0[t + 4]);
                a[mi][3] = f2tf32(ar1[t + 4]);
            }
            float bf[4][2];
            #pragma unroll
            for (int ni = 0; ni < 4; ni++) {
                bf[ni][0] = f2tf32(Wb[(kb + t) * WSL + wn + ni * 8 + g]);
                bf[ni][1] = f2tf32(Wb[(kb + t + 4) * WSL + wn + ni * 8 + g]);
            }
            #pragma unroll
            for (int mi = 0; mi < 2; mi++)
                #pragma unroll
                for (int ni = 0; ni < 4; ni++)
                    mma_tf32(acc[mi][ni][0], acc[mi][ni][1],
                             acc[mi][ni][2], acc[mi][ni][3],
                             a[mi][0], a[mi][1], a[mi][2], a[mi][3],
                             bf[ni][0], bf[ni][1]);
        }
        __syncthreads();
    }

    float* qkv = (z == 0) ? g_Q : (z == 1) ? g_K : g_V;
    #pragma unroll
    for (int mi = 0; mi < 2; mi++) {
        int r0 = bm + wm + mi * 16 + g;
        int r1 = r0 + 8;
        #pragma unroll
        for (int ni = 0; ni < 4; ni++) {
            int col = bn + wn + ni * 8 + 2 * t;
            if (mode == 3) {
                float2 bb = *(const float2*)&bias[col];
                *(float2*)&dst[(size_t)r0 * D_ + col] =
                    make_float2(acc[mi][ni][0] + bb.x, acc[mi][ni][1] + bb.y);
                *(float2*)&dst[(size_t)r1 * D_ + col] =
                    make_float2(acc[mi][ni][2] + bb.x, acc[mi][ni][3] + bb.y);
            } else {
                int h = col / DH_, c = col - h * DH_;
                int b0r = r0 / N_, n0r = r0 - b0r * N_;
                int b1r = r1 / N_, n1r = r1 - b1r * N_;
                *(float2*)&qkv[(((size_t)(b0r * H_ + h)) * N_ + n0r) * DH_ + c] =
                    make_float2(f2tf32(acc[mi][ni][0] * scale),
                                f2tf32(acc[mi][ni][1] * scale));
                *(float2*)&qkv[(((size_t)(b1r * H_ + h)) * N_ + n1r) * DH_ + c] =
                    make_float2(f2tf32(acc[mi][ni][2] * scale),
                                f2tf32(acc[mi][ni][3] * scale));
            }
        }
    }
}

// ---------------- tensor-core flash attention, split-K x2 ----------------
// grid (N/128, BH, SPLIT). blockIdx.z selects a half of the key range.
// Each block writes unnormalized (sum p*V, sum p) partials.
#define KT 32
#define KS 44
#define VS 40
#define PS 36
#define NTL (N_ / KT / SPLIT)   // 48 tiles per block

__global__ __launch_bounds__(128) void attn_kernel() {
    __shared__ float Ksm[2][KT * KS];
    __shared__ float Vsm[2][KT * VS];
    __shared__ float Psm[4][32 * PS];
    __shared__ unsigned char m2s[2][KT];

    const int bh = blockIdx.y;
    const int zz = blockIdx.z;
    const int b  = bh >> 3;
    const int tid  = threadIdx.x;
    const int w    = tid >> 5;
    const int lane = tid & 31;
    const int g = lane >> 2;
    const int t = lane & 3;
    const int q0 = blockIdx.x * 128 + w * 32;
    const int tile0 = zz * NTL;

    const float* Qb = g_Q + (size_t)bh * N_ * DH_;
    const float* Kb = g_K + (size_t)bh * N_ * DH_;
    const float* Vb = g_V + (size_t)bh * N_ * DH_;
    const unsigned char* M2b = g_M2 + b * N_;

    float aq[2][5][4];
    bool m1f[2][2];
    #pragma unroll
    for (int mi = 0; mi < 2; mi++) {
        const float* qr0 = Qb + (size_t)(q0 + mi * 16 + g) * DH_;
        const float* qr1 = Qb + (size_t)(q0 + mi * 16 + g + 8) * DH_;
        #pragma unroll
        for (int ks = 0; ks < 5; ks++) {
            aq[mi][ks][0] = qr0[8 * ks + t];
            aq[mi][ks][1] = qr1[8 * ks + t];
            aq[mi][ks][2] = qr0[8 * ks + t + 4];
            aq[mi][ks][3] = qr1[8 * ks + t + 4];
        }
        m1f[mi][0] = g_M1[b * N_ + q0 + mi * 16 + g] != 0;
        m1f[mi][1] = g_M1[b * N_ + q0 + mi * 16 + g + 8] != 0;
    }

    float o[2][5][4];
    float l[2][2];
    #pragma unroll
    for (int mi = 0; mi < 2; mi++) {
        l[mi][0] = 0.f; l[mi][1] = 0.f;
        #pragma unroll
        for (int i = 0; i < 5; i++)
            #pragma unroll
            for (int r = 0; r < 4; r++) o[mi][i][r] = 0.f;
    }

    auto issue = [&](int tile, int bufi) {
        const float* Ksrc = Kb + (size_t)tile * KT * DH_;
        const float4* vg = (const float4*)(Vb + (size_t)tile * KT * DH_);
        uint32_t kdst = (uint32_t)__cvta_generic_to_shared(&Ksm[bufi][0]);
        uint32_t vdst = (uint32_t)__cvta_generic_to_shared(&Vsm[bufi][0]);
        #pragma unroll
        for (int i = 0; i < 3; i++) {
            int c = tid + i * 128;
            if (c < 320) {
                int key = c / 10, f4 = c - key * 10;
                cpa16(kdst + (uint32_t)(key * KS + f4 * 4) * 4,
                      Ksrc + key * DH_ + f4 * 4);
                cpa16(vdst + (uint32_t)c * 16, vg + c);   // dense: VS == DH_
            }
        }
        if (tid < 2) {
            uint32_t mdst = (uint32_t)__cvta_generic_to_shared(&m2s[bufi][0]);
            cpa16(mdst + tid * 16, M2b + tile * KT + tid * 16);
        }
    };

    issue(tile0, 0);
    asm volatile("cp.async.commit_group;");

    for (int it = 0; it < NTL; it++) {
        int buf = it & 1;
        if (it + 1 < NTL) {
            issue(tile0 + it + 1, buf ^ 1);
            asm volatile("cp.async.commit_group;");
            asm volatile("cp.async.wait_group 1;");
        } else {
            asm volatile("cp.async.wait_group 0;");
        }
        __syncthreads();

        const float* Kt = &Ksm[buf][0];
        const float* Vt = &Vsm[buf][0];
        float* Pw = &Psm[w][0];

        // ---- scores: S[32,32] = Q @ K^T; K fragments reused across mi
        #pragma unroll
        for (int nb = 0; nb < 4; nb++) {
            float bfr[5][2];
            const float* krow = Kt + (nb * 8 + g) * KS;
            #pragma unroll
            for (int ks = 0; ks < 5; ks++) {
                bfr[ks][0] = krow[8 * ks + t];
                bfr[ks][1] = krow[8 * ks + 4 + t];
            }
            bool mc0 = m2s[buf][nb * 8 + 2 * t] != 0;
            bool mc1 = m2s[buf][nb * 8 + 2 * t + 1] != 0;
            #pragma unroll
            for (int mi = 0; mi < 2; mi++) {
                float d0 = 0.f, d1 = 0.f, d2 = 0.f, d3 = 0.f;
                #pragma unroll
                for (int ks = 0; ks < 5; ks++)
                    mma_tf32(d0, d1, d2, d3,
                             aq[mi][ks][0], aq[mi][ks][1],
                             aq[mi][ks][2], aq[mi][ks][3],
                             bfr[ks][0], bfr[ks][1]);
                float p0 = (m1f[mi][0] && mc0) ? 0.f : __expf(d0);
                float p1 = (m1f[mi][0] && mc1) ? 0.f : __expf(d1);
                float p2 = (m1f[mi][1] && mc0) ? 0.f : __expf(d2);
                float p3 = (m1f[mi][1] && mc1) ? 0.f : __expf(d3);
                l[mi][0] += p0 + p1;
                l[mi][1] += p2 + p3;
                *(float2*)&Pw[(mi * 16 + g) * PS + nb * 8 + 2 * t] =
                    make_float2(f2tf32(p0), f2tf32(p1));
                *(float2*)&Pw[(mi * 16 + g + 8) * PS + nb * 8 + 2 * t] =
                    make_float2(f2tf32(p2), f2tf32(p3));
            }
        }
        __syncwarp();

        // ---- O += P @ V; V fragments reused across mi
        #pragma unroll
        for (int kb = 0; kb < 4; kb++) {
            float bv[5][2];
            const float* vr0 = Vt + (kb * 8 + t) * VS;
            const float* vr1 = Vt + (kb * 8 + t + 4) * VS;
            #pragma unroll
            for (int nbo = 0; nbo < 5; nbo++) {
                bv[nbo][0] = vr0[nbo * 8 + g];
                bv[nbo][1] = vr1[nbo * 8 + g];
            }
            #pragma unroll
            for (int mi = 0; mi < 2; mi++) {
                float a0 = Pw[(mi * 16 + g) * PS + kb * 8 + t];
                float a1 = Pw[(mi * 16 + g + 8) * PS + kb * 8 + t];
                float a2 = Pw[(mi * 16 + g) * PS + kb * 8 + t + 4];
                float a3 = Pw[(mi * 16 + g + 8) * PS + kb * 8 + t + 4];
                #pragma unroll
                for (int nbo = 0; nbo < 5; nbo++)
                    mma_tf32(o[mi][nbo][0], o[mi][nbo][1],
                             o[mi][nbo][2], o[mi][nbo][3],
                             a0, a1, a2, a3, bv[nbo][0], bv[nbo][1]);
            }
        }
        __syncwarp();
        __syncthreads();
    }

    // ---- reduce row sums across quads, store UNNORMALIZED partials
    float* Pob = g_Po + ((size_t)zz * BH_ + bh) * N_ * DH_;
    float* Plb = g_Pl + ((size_t)zz * BH_ + bh) * N_;
    #pragma unroll
    for (int mi = 0; mi < 2; mi++) {
        l[mi][0] += __shfl_xor_sync(0xffffffffu, l[mi][0], 1);
        l[mi][0] += __shfl_xor_sync(0xffffffffu, l[mi][0], 2);
        l[mi][1] += __shfl_xor_sync(0xffffffffu, l[mi][1], 1);
        l[mi][1] += __shfl_xor_sync(0xffffffffu, l[mi][1], 2);

        int r0 = q0 + mi * 16 + g;
        int r1 = r0 + 8;
        if (t == 0) {
            Plb[r0] = l[mi][0];
            Plb[r1] = l[mi][1];
        }
        float* O0 = Pob + (size_t)r0 * DH_;
        float* O1 = Pob + (size_t)r1 * DH_;
        #pragma unroll
        for (int nbo = 0; nbo < 5; nbo++) {
            *(float2*)&O0[nbo * 8 + 2 * t] = make_float2(o[mi][nbo][0], o[mi][nbo][1]);
            *(float2*)&O1[nbo * 8 + 2 * t] = make_float2(o[mi][nbo][2], o[mi][nbo][3]);
        }
    }
}

// ---------------- combine: sum split-K partials, normalize, write g_O ------
#define CMB_TOT (BH_ * N_ * (DH_ / 4))   // one thread per float4

__global__ void combine_kernel() {
    int idx = blockIdx.x * 256 + threadIdx.x;
    if (idx >= CMB_TOT) return;
    int row = idx / (DH_ / 4);
    int c4 = idx - row * (DH_ / 4);
    int bh = row / N_, n = row - bh * N_;
    int b = bh >> 3, h = bh & 7;

    float l = g_Pl[row] + g_Pl[BH_ * N_ + row];
    float4 o0 = *(const float4*)&g_Po[(size_t)row * DH_ + c4 * 4];
    float4 o1 = *(const float4*)&g_Po[((size_t)BH_ * N_ + row) * DH_ + c4 * 4];
    float4 r;
    if (l > 0.f) {
        float inv = 1.f / l;
        r.x = (o0.x + o1.x) * inv;
        r.y = (o0.y + o1.y) * inv;
        r.z = (o0.z + o1.z) * inv;
        r.w = (o0.w + o1.w) * inv;
    } else {
        // all keys masked: reference softmax -> uniform -> mean of V
        const float* Vb = g_V + (size_t)bh * N_ * DH_ + c4 * 4;
        float s0 = 0.f, s1 = 0.f, s2 = 0.f, s3 = 0.f;
        for (int j = 0; j < N_; j++) {
            const float* vr = Vb + (size_t)j * DH_;
            s0 += vr[0]; s1 += vr[1]; s2 += vr[2]; s3 += vr[3];
        }
        float inv = 1.f / (float)N_;
        r = make_float4(s0 * inv, s1 * inv, s2 * inv, s3 * inv);
    }
    *(float4*)&g_O[((size_t)b * N_ + n) * D_ + h * DH_ + c4 * 4] = r;
}

// ---------------- launch ----------------
extern "C" void kernel_launch(void* const* d_in, const int* in_sizes, int n_in,
                              void* d_out, int out_size) {
    (void)in_sizes; (void)n_in; (void)out_size;
    const float* x     = (const float*)d_in[0];
    const float* ctx   = (const float*)d_in[1];
    const float* mask1 = (const float*)d_in[2];
    const float* mask2 = (const float*)d_in[3];
    const float* Wq    = (const float*)d_in[4];
    const float* Wk    = (const float*)d_in[5];
    const float* Wv    = (const float*)d_in[6];
    const float* Wo    = (const float*)d_in[7];
    const float* bo    = (const float*)d_in[8];
    float* out = (float*)d_out;

    dim3 gqkv(D_ / TBN, (B_ * N_) / TBM, 3);   // (5, 96, 3)
    dim3 gout(D_ / TBN, (B_ * N_) / TBM, 1);

    mask_kernel<<<(B_ * N_ + 255) / 256, 256>>>(mask1, mask2);
    gemm_tf32_kernel<<<gqkv, 128>>>(x, ctx, Wq, Wk, Wv, nullptr, 0, nullptr);
    attn_kernel<<<dim3(N_ / 128, BH_, SPLIT), 128>>>();
    combine_kernel<<<(CMB_TOT + 255) / 256, 256>>>();
    gemm_tf32_kernel<<<gout, 128>>>(nullptr, nullptr, Wo, nullptr, nullptr, bo, 3, out);
}

// round 15
// speedup vs baseline: 1.2144x; 1.2144x over previous
#include <cuda_runtime.h>
#include <math.h>
#include <stdint.h>

// Problem constants
#define B_   2
#define N_   3072
#define D_   320
#define H_   8
#define DH_  40
#define DHP_ 48     // padded head dim for Q/K (col 40 = mask, 41..47 = 0)
#define BH_  16
#define SCALE_ 0.15811388300841898f   // 40^-0.5
#define MASKNEG -60.0f

// ---------------- scratch (no allocation allowed) ----------------
__device__ float g_Q[BH_ * N_ * DHP_];  // [bh, n, 48], pre-scaled, tf32-rounded
__device__ float g_K[BH_ * N_ * DHP_];  // [bh, n, 48], tf32-rounded
__device__ float g_V[BH_ * N_ * DH_];   // [bh, n, 40], tf32-rounded
__device__ float g_O[B_ * N_ * D_];     // attention output, [b, n, h*40+c]

// ---------------- helpers ----------------
__device__ __forceinline__ float f2tf32(float x) {
    uint32_t u;
    asm("cvt.rna.tf32.f32 %0, %1;" : "=r"(u) : "f"(x));
    return __uint_as_float(u);
}

__device__ __forceinline__ void mma_tf32(
    float& d0, float& d1, float& d2, float& d3,
    float a0, float a1, float a2, float a3,
    float b0, float b1)
{
    asm volatile(
        "mma.sync.aligned.m16n8k8.row.col.f32.tf32.tf32.f32 "
        "{%0,%1,%2,%3}, {%4,%5,%6,%7}, {%8,%9}, {%0,%1,%2,%3};"
        : "+f"(d0), "+f"(d1), "+f"(d2), "+f"(d3)
        : "r"(__float_as_uint(a0)), "r"(__float_as_uint(a1)),
          "r"(__float_as_uint(a2)), "r"(__float_as_uint(a3)),
          "r"(__float_as_uint(b0)), "r"(__float_as_uint(b1)));
}

__device__ __forceinline__ void cpa16(uint32_t dst, const void* src) {
    asm volatile("cp.async.ca.shared.global [%0], [%1], 16;" :: "r"(dst), "l"(src));
}

// ---------------- mask kernel: writes Q/K pad columns 40..47 ----------------
// nearest_resize(mask, 64, 48) from (512,384): stride exactly 8 in both dims.
__global__ void mask_kernel(const float* __restrict__ mask1,
                            const float* __restrict__ mask2) {
    int idx = blockIdx.x * 256 + threadIdx.x;
    if (idx >= B_ * N_) return;
    int b = idx / N_, i = idx - b * N_;
    int y = i / 48, x = i - y * 48;
    size_t src = ((size_t)b * 512 + (size_t)y * 8) * 384 + (size_t)x * 8;
    float qv = (mask1[src] >= 0.5f) ? 1.0f : 0.0f;
    float kv = (mask2[src] >= 0.5f) ? MASKNEG : 0.0f;
    float4 qp = make_float4(qv, 0.f, 0.f, 0.f);
    float4 kp = make_float4(kv, 0.f, 0.f, 0.f);
    float4 zz = make_float4(0.f, 0.f, 0.f, 0.f);
    #pragma unroll
    for (int h = 0; h < H_; h++) {
        size_t row = ((size_t)(b * H_ + h) * N_ + i) * DHP_;
        *(float4*)&g_Q[row + 40] = qp;
        *(float4*)&g_Q[row + 44] = zz;
        *(float4*)&g_K[row + 40] = kp;
        *(float4*)&g_K[row + 44] = zz;
    }
}

// ---------------- tf32 tensor-core GEMM (R10 known-good form) --------------
// mode 0: QKV fused (blockIdx.z = 0/1/2 -> Q/K/V), scatter + tf32 round
// mode 3: A = g_O, dst = acc + bias
#define TBM 64
#define TBN 64
#define TBK 16
#define ASL 20      // As [m][k] stride: banks (20g+t) mod 32 all distinct
#define WSL 72      // Ws [k][n] stride: banks (8t+g)  mod 32 all distinct
#define NKT (D_ / TBK)   // 20 k-tiles

__global__ __launch_bounds__(128) void gemm_tf32_kernel(
    const float* __restrict__ x, const float* __restrict__ ctx,
    const float* __restrict__ Wq, const float* __restrict__ Wk,
    const float* __restrict__ Wv, const float* __restrict__ bias,
    int mode, float* __restrict__ dst)
{
    __shared__ float As[2][TBM * ASL];
    __shared__ float Ws[2][TBK * WSL];

    const int z = blockIdx.z;
    const float* Ain;
    const float* W;
    float scale;
    if (mode == 3) { Ain = (const float*)g_O; W = Wq; scale = 1.f; }
    else {
        Ain = (z == 0) ? x : ctx;
        W = (z == 0) ? Wq : (z == 1) ? Wk : Wv;
        scale = (z == 0) ? SCALE_ : 1.f;
    }

    const int bm = blockIdx.y * TBM;
    const int bn = blockIdx.x * TBN;
    const int tid = threadIdx.x;
    const int w = tid >> 5, lane = tid & 31;
    const int g = lane >> 2, t = lane & 3;
    const int wm = (w & 1) * 32;
    const int wn = (w >> 1) * 32;

    float acc[2][4][4];
    #pragma unroll
    for (int mi = 0; mi < 2; mi++)
        #pragma unroll
        for (int ni = 0; ni < 4; ni++)
            #pragma unroll
            for (int r = 0; r < 4; r++) acc[mi][ni][r] = 0.f;

    auto issue = [&](int k0, int bufi) {
        uint32_t abase = (uint32_t)__cvta_generic_to_shared(&As[bufi][0]);
        uint32_t wbase = (uint32_t)__cvta_generic_to_shared(&Ws[bufi][0]);
        #pragma unroll
        for (int i = 0; i < 2; i++) {
            int ch = tid * 2 + i;
            int r = ch >> 2, c = (ch & 3) * 4;
            cpa16(abase + (uint32_t)(r * ASL + c) * 4,
                  Ain + (size_t)(bm + r) * D_ + k0 + c);
        }
        #pragma unroll
        for (int i = 0; i < 2; i++) {
            int ch = tid * 2 + i;
            int r = ch >> 4, c = (ch & 15) * 4;
            cpa16(wbase + (uint32_t)(r * WSL + c) * 4,
                  W + (size_t)(k0 + r) * D_ + bn + c);
        }
    };

    issue(0, 0);
    asm volatile("cp.async.commit_group;");

    for (int kt = 0; kt < NKT; kt++) {
        int buf = kt & 1;
        if (kt + 1 < NKT) {
            issue((kt + 1) * TBK, buf ^ 1);
            asm volatile("cp.async.commit_group;");
            asm volatile("cp.async.wait_group 1;");
        } else {
            asm volatile("cp.async.wait_group 0;");
        }
        __syncthreads();

        const float* Ab = &As[buf][0];
        const float* Wb = &Ws[buf][0];

        #pragma unroll
        for (int kk = 0; kk < 2; kk++) {
            const int kb = kk * 8;
            float a[2][4];
            #pragma unroll
            for (int mi = 0; mi < 2; mi++) {
                const float* ar0 = Ab + (wm + mi * 16 + g) * ASL + kb;
                const float* ar1 = Ab + (wm + mi * 16 + g + 8) * ASL + kb;
                a[mi][0] = f2tf32(ar0[t]);
                a[mi][1] = f2tf32(ar1[t]);
                a[mi][2] = f2tf32(ar0[t + 4]);
                a[mi][3] = f2tf32(ar1[t + 4]);
            }
            float bf[4][2];
            #pragma unroll
            for (int ni = 0; ni < 4; ni++) {
                bf[ni][0] = f2tf32(Wb[(kb + t) * WSL + wn + ni * 8 + g]);
                bf[ni][1] = f2tf32(Wb[(kb + t + 4) * WSL + wn + ni * 8 + g]);
            }
            #pragma unroll
            for (int mi = 0; mi < 2; mi++)
                #pragma unroll
                for (int ni = 0; ni < 4; ni++)
                    mma_tf32(acc[mi][ni][0], acc[mi][ni][1],
                             acc[mi][ni][2], acc[mi][ni][3],
                             a[mi][0], a[mi][1], a[mi][2], a[mi][3],
                             bf[ni][0], bf[ni][1]);
        }
        __syncthreads();
    }

    #pragma unroll
    for (int mi = 0; mi < 2; mi++) {
        int r0 = bm + wm + mi * 16 + g;
        int r1 = r0 + 8;
        #pragma unroll
        for (int ni = 0; ni < 4; ni++) {
            int col = bn + wn + ni * 8 + 2 * t;
            if (mode == 3) {
                float2 bb = *(const float2*)&bias[col];
                *(float2*)&dst[(size_t)r0 * D_ + col] =
                    make_float2(acc[mi][ni][0] + bb.x, acc[mi][ni][1] + bb.y);
                *(float2*)&dst[(size_t)r1 * D_ + col] =
                    make_float2(acc[mi][ni][2] + bb.x, acc[mi][ni][3] + bb.y);
            } else {
                float* qkv = (z == 0) ? g_Q : (z == 1) ? g_K : g_V;
                int qs = (z == 2) ? DH_ : DHP_;
                int h = col / DH_, c = col - h * DH_;
                int b0r = r0 / N_, n0r = r0 - b0r * N_;
                int b1r = r1 / N_, n1r = r1 - b1r * N_;
                *(float2*)&qkv[(((size_t)(b0r * H_ + h)) * N_ + n0r) * qs + c] =
                    make_float2(f2tf32(acc[mi][ni][0] * scale),
                                f2tf32(acc[mi][ni][1] * scale));
                *(float2*)&qkv[(((size_t)(b1r * H_ + h)) * N_ + n1r) * qs + c] =
                    make_float2(f2tf32(acc[mi][ni][2] * scale),
                                f2tf32(acc[mi][ni][3] * scale));
            }
        }
    }
}

// ---------------- tensor-core flash attention (tf32 mma, mask-in-MMA) ------
// 32 query rows per warp, 4 warps = 128 queries/block. Scores use 6 k8-steps
// over the padded 48 cols; step 5 adds -60*(m1&m2) from the pad columns.
#define KT 32
#define KS 52          // K smem stride (rows by g: banks (20g+t) distinct)
#define VS 40          // V dense (rows by t: banks (8t+g) distinct)
#define PS 36
#define NT (N_ / KT)   // 96 tiles

__global__ __launch_bounds__(128) void attn_kernel() {
    __shared__ float Ksm[2][KT * KS];
    __shared__ float Vsm[2][KT * VS];
    __shared__ float Psm[4][32 * PS];

    const int bh = blockIdx.y;
    const int b  = bh >> 3;
    const int h  = bh & 7;
    const int tid  = threadIdx.x;
    const int w    = tid >> 5;
    const int lane = tid & 31;
    const int g = lane >> 2;
    const int t = lane & 3;
    const int q0 = blockIdx.x * 128 + w * 32;

    const float* Qb = g_Q + (size_t)bh * N_ * DHP_;
    const float* Kb = g_K + (size_t)bh * N_ * DHP_;
    const float* Vb = g_V + (size_t)bh * N_ * DH_;

    float aq[2][6][4];
    #pragma unroll
    for (int mi = 0; mi < 2; mi++) {
        const float* qr0 = Qb + (size_t)(q0 + mi * 16 + g) * DHP_;
        const float* qr1 = Qb + (size_t)(q0 + mi * 16 + g + 8) * DHP_;
        #pragma unroll
        for (int ks = 0; ks < 6; ks++) {
            aq[mi][ks][0] = qr0[8 * ks + t];
            aq[mi][ks][1] = qr1[8 * ks + t];
            aq[mi][ks][2] = qr0[8 * ks + t + 4];
            aq[mi][ks][3] = qr1[8 * ks + t + 4];
        }
    }

    float o[2][5][4];
    float l[2][2];
    #pragma unroll
    for (int mi = 0; mi < 2; mi++) {
        l[mi][0] = 0.f; l[mi][1] = 0.f;
        #pragma unroll
        for (int i = 0; i < 5; i++)
            #pragma unroll
            for (int r = 0; r < 4; r++) o[mi][i][r] = 0.f;
    }

    auto issue = [&](int tile, int bufi) {
        const float* Ksrc = Kb + (size_t)tile * KT * DHP_;
        const float4* vg = (const float4*)(Vb + (size_t)tile * KT * DH_);
        uint32_t kdst = (uint32_t)__cvta_generic_to_shared(&Ksm[bufi][0]);
        uint32_t vdst = (uint32_t)__cvta_generic_to_shared(&Vsm[bufi][0]);
        #pragma unroll
        for (int i = 0; i < 3; i++) {
            int c = tid + i * 128;                 // 0..383: exactly K tile
            int krow = c / 12, kf4 = c - krow * 12;
            cpa16(kdst + (uint32_t)(krow * KS + kf4 * 4) * 4,
                  Ksrc + krow * DHP_ + kf4 * 4);
            if (c < 320)
                cpa16(vdst + (uint32_t)c * 16, vg + c);   // dense: VS == DH_
        }
    };

    issue(0, 0);
    asm volatile("cp.async.commit_group;");

    for (int tile = 0; tile < NT; tile++) {
        int buf = tile & 1;
        if (tile + 1 < NT) {
            issue(tile + 1, buf ^ 1);
            asm volatile("cp.async.commit_group;");
            asm volatile("cp.async.wait_group 1;");
        } else {
            asm volatile("cp.async.wait_group 0;");
        }
        __syncthreads();

        const float* Kt = &Ksm[buf][0];
        const float* Vt = &Vsm[buf][0];
        float* Pw = &Psm[w][0];

        // ---- scores: S[32,32] = Qp @ Kp^T (mask included); K frags shared
        #pragma unroll
        for (int nb = 0; nb < 4; nb++) {
            float bfr[6][2];
            const float* krow = Kt + (nb * 8 + g) * KS;
            #pragma unroll
            for (int ks = 0; ks < 6; ks++) {
                bfr[ks][0] = krow[8 * ks + t];
                bfr[ks][1] = krow[8 * ks + 4 + t];
            }
            #pragma unroll
            for (int mi = 0; mi < 2; mi++) {
                float d0 = 0.f, d1 = 0.f, d2 = 0.f, d3 = 0.f;
                #pragma unroll
                for (int ks = 0; ks < 6; ks++)
                    mma_tf32(d0, d1, d2, d3,
                             aq[mi][ks][0], aq[mi][ks][1],
                             aq[mi][ks][2], aq[mi][ks][3],
                             bfr[ks][0], bfr[ks][1]);
                float p0 = __expf(d0);
                float p1 = __expf(d1);
                float p2 = __expf(d2);
                float p3 = __expf(d3);
                l[mi][0] += p0 + p1;
                l[mi][1] += p2 + p3;
                *(float2*)&Pw[(mi * 16 + g) * PS + nb * 8 + 2 * t] =
                    make_float2(p0, p1);
                *(float2*)&Pw[(mi * 16 + g + 8) * PS + nb * 8 + 2 * t] =
                    make_float2(p2, p3);
            }
        }
        __syncwarp();

        // ---- O += P @ V; V fragments reused across mi
        #pragma unroll
        for (int kb = 0; kb < 4; kb++) {
            float bv[5][2];
            const float* vr0 = Vt + (kb * 8 + t) * VS;
            const float* vr1 = Vt + (kb * 8 + t + 4) * VS;
            #pragma unroll
            for (int nbo = 0; nbo < 5; nbo++) {
                bv[nbo][0] = vr0[nbo * 8 + g];
                bv[nbo][1] = vr1[nbo * 8 + g];
            }
            #pragma unroll
            for (int mi = 0; mi < 2; mi++) {
                float a0 = Pw[(mi * 16 + g) * PS + kb * 8 + t];
                float a1 = Pw[(mi * 16 + g + 8) * PS + kb * 8 + t];
                float a2 = Pw[(mi * 16 + g) * PS + kb * 8 + t + 4];
                float a3 = Pw[(mi * 16 + g + 8) * PS + kb * 8 + t + 4];
                #pragma unroll
                for (int nbo = 0; nbo < 5; nbo++)
                    mma_tf32(o[mi][nbo][0], o[mi][nbo][1],
                             o[mi][nbo][2], o[mi][nbo][3],
                             a0, a1, a2, a3, bv[nbo][0], bv[nbo][1]);
            }
        }
        __syncwarp();
        __syncthreads();
    }

    // ---- reduce row sums across quads, normalize, write
    // All-masked rows give l ~ 1e-23 (< 1e-15) -> uniform mean-V fallback.
    #pragma unroll
    for (int mi = 0; mi < 2; mi++) {
        l[mi][0] += __shfl_xor_sync(0xffffffffu, l[mi][0], 1);
        l[mi][0] += __shfl_xor_sync(0xffffffffu, l[mi][0], 2);
        l[mi][1] += __shfl_xor_sync(0xffffffffu, l[mi][1], 1);
        l[mi][1] += __shfl_xor_sync(0xffffffffu, l[mi][1], 2);

        float inv0, inv1;
        if (l[mi][0] > 1e-15f) {
            inv0 = 1.f / l[mi][0];
        } else {
            #pragma unroll
            for (int nbo = 0; nbo < 5; nbo++) { o[mi][nbo][0] = 0.f; o[mi][nbo][1] = 0.f; }
            for (int j = 0; j < N_; j++) {
                const float* vr = Vb + (size_t)j * DH_;
                #pragma unroll
                for (int nbo = 0; nbo < 5; nbo++) {
                    o[mi][nbo][0] += vr[nbo * 8 + 2 * t];
                    o[mi][nbo][1] += vr[nbo * 8 + 2 * t + 1];
                }
            }
            inv0 = 1.f / (float)N_;
        }
        if (l[mi][1] > 1e-15f) {
            inv1 = 1.f / l[mi][1];
        } else {
            #pragma unroll
            for (int nbo = 0; nbo < 5; nbo++) { o[mi][nbo][2] = 0.f; o[mi][nbo][3] = 0.f; }
            for (int j = 0; j < N_; j++) {
                const float* vr = Vb + (size_t)j * DH_;
                #pragma unroll
                for (int nbo = 0; nbo < 5; nbo++) {
                    o[mi][nbo][2] += vr[nbo * 8 + 2 * t];
                    o[mi][nbo][3] += vr[nbo * 8 + 2 * t + 1];
                }
            }
            inv1 = 1.f / (float)N_;
        }

        float* O0 = g_O + (size_t)(b * N_ + q0 + mi * 16 + g) * D_ + h * DH_;
        float* O1 = g_O + (size_t)(b * N_ + q0 + mi * 16 + g + 8) * D_ + h * DH_;
        #pragma unroll
        for (int nbo = 0; nbo < 5; nbo++) {
            *(float2*)&O0[nbo * 8 + 2 * t] =
                make_float2(o[mi][nbo][0] * inv0, o[mi][nbo][1] * inv0);
            *(float2*)&O1[nbo * 8 + 2 * t] =
                make_float2(o[mi][nbo][2] * inv1, o[mi][nbo][3] * inv1);
        }
    }
}

// ---------------- launch ----------------
extern "C" void kernel_launch(void* const* d_in, const int* in_sizes, int n_in,
                              void* d_out, int out_size) {
    (void)in_sizes; (void)n_in; (void)out_size;
    const float* x     = (const float*)d_in[0];
    const float* ctx   = (const float*)d_in[1];
    const float* mask1 = (const float*)d_in[2];
    const float* mask2 = (const float*)d_in[3];
    const float* Wq    = (const float*)d_in[4];
    const float* Wk    = (const float*)d_in[5];
    const float* Wv    = (const float*)d_in[6];
    const float* Wo    = (const float*)d_in[7];
    const float* bo    = (const float*)d_in[8];
    float* out = (float*)d_out;

    dim3 gqkv(D_ / TBN, (B_ * N_) / TBM, 3);   // (5, 96, 3)
    dim3 gout(D_ / TBN, (B_ * N_) / TBM, 1);

    mask_kernel<<<(B_ * N_ + 255) / 256, 256>>>(mask1, mask2);
    gemm_tf32_kernel<<<gqkv, 128>>>(x, ctx, Wq, Wk, Wv, nullptr, 0, nullptr);
    attn_kernel<<<dim3(N_ / 128, BH_), 128>>>();
    gemm_tf32_kernel<<<gout, 128>>>(nullptr, nullptr, Wo, nullptr, nullptr, bo, 3, out);
}

// round 16
// speedup vs baseline: 1.2274x; 1.0107x over previous
#include <cuda_runtime.h>
#include <math.h>
#include <stdint.h>

// Problem constants
#define B_   2
#define N_   3072
#define D_   320
#define H_   8
#define DH_  40
#define DHP_ 48     // padded head dim for Q/K (col 40 = mask, 41..47 = 0)
#define BH_  16
#define SCALE_ 0.15811388300841898f   // 40^-0.5
#define MASKNEG -60.0f

// K is stored FRAGMENT-MAJOR within each 48-float row:
//   logical col c (0..47): ks=c>>3, r=c&7, t=r&3, half=r>>2
//   pos(c) = t*12 + ks*2 + half
// so thread t's six k8-fragments are 12 contiguous floats at offset t*12.
__host__ __device__ __forceinline__ int kperm(int c) {
    return (c & 3) * 12 + (c >> 3) * 2 + ((c >> 2) & 1);
}

// ---------------- scratch (no allocation allowed) ----------------
__device__ float g_Q[BH_ * N_ * DHP_];  // [bh, n, 48] plain, pre-scaled, tf32
__device__ float g_K[BH_ * N_ * DHP_];  // [bh, n, 48] fragment-major, tf32
__device__ float g_V[BH_ * N_ * DH_];   // [bh, n, 40] plain, tf32
__device__ float g_O[B_ * N_ * D_];     // attention output, [b, n, h*40+c]

// ---------------- helpers ----------------
__device__ __forceinline__ float f2tf32(float x) {
    uint32_t u;
    asm("cvt.rna.tf32.f32 %0, %1;" : "=r"(u) : "f"(x));
    return __uint_as_float(u);
}

__device__ __forceinline__ void mma_tf32(
    float& d0, float& d1, float& d2, float& d3,
    float a0, float a1, float a2, float a3,
    float b0, float b1)
{
    asm volatile(
        "mma.sync.aligned.m16n8k8.row.col.f32.tf32.tf32.f32 "
        "{%0,%1,%2,%3}, {%4,%5,%6,%7}, {%8,%9}, {%0,%1,%2,%3};"
        : "+f"(d0), "+f"(d1), "+f"(d2), "+f"(d3)
        : "r"(__float_as_uint(a0)), "r"(__float_as_uint(a1)),
          "r"(__float_as_uint(a2)), "r"(__float_as_uint(a3)),
          "r"(__float_as_uint(b0)), "r"(__float_as_uint(b1)));
}

__device__ __forceinline__ void cpa16(uint32_t dst, const void* src) {
    asm volatile("cp.async.ca.shared.global [%0], [%1], 16;" :: "r"(dst), "l"(src));
}

// ---------------- mask kernel: writes Q/K pad columns 40..47 ----------------
__global__ void mask_kernel(const float* __restrict__ mask1,
                            const float* __restrict__ mask2) {
    int idx = blockIdx.x * 256 + threadIdx.x;
    if (idx >= B_ * N_) return;
    int b = idx / N_, i = idx - b * N_;
    int y = i / 48, x = i - y * 48;
    size_t src = ((size_t)b * 512 + (size_t)y * 8) * 384 + (size_t)x * 8;
    float qv = (mask1[src] >= 0.5f) ? 1.0f : 0.0f;
    float kv = (mask2[src] >= 0.5f) ? MASKNEG : 0.0f;
    float4 qp = make_float4(qv, 0.f, 0.f, 0.f);
    float4 zz = make_float4(0.f, 0.f, 0.f, 0.f);
    #pragma unroll
    for (int h = 0; h < H_; h++) {
        size_t row = ((size_t)(b * H_ + h) * N_ + i) * DHP_;
        *(float4*)&g_Q[row + 40] = qp;
        *(float4*)&g_Q[row + 44] = zz;
        #pragma unroll
        for (int u = 0; u < 8; u++)
            g_K[row + kperm(40 + u)] = (u == 0) ? kv : 0.f;
    }
}

// ---------------- tf32 tensor-core GEMM ----------------
// mode 0: QKV fused (blockIdx.z = 0/1/2 -> Q/K/V); K scattered fragment-major
// mode 3: A = g_O, dst = acc + bias
#define TBM 64
#define TBN 64
#define TBK 16
#define ASL 20
#define WSL 72
#define NKT (D_ / TBK)

__global__ __launch_bounds__(128) void gemm_tf32_kernel(
    const float* __restrict__ x, const float* __restrict__ ctx,
    const float* __restrict__ Wq, const float* __restrict__ Wk,
    const float* __restrict__ Wv, const float* __restrict__ bias,
    int mode, float* __restrict__ dst)
{
    __shared__ float As[2][TBM * ASL];
    __shared__ float Ws[2][TBK * WSL];

    const int z = blockIdx.z;
    const float* Ain;
    const float* W;
    float scale;
    if (mode == 3) { Ain = (const float*)g_O; W = Wq; scale = 1.f; }
    else {
        Ain = (z == 0) ? x : ctx;
        W = (z == 0) ? Wq : (z == 1) ? Wk : Wv;
        scale = (z == 0) ? SCALE_ : 1.f;
    }

    const int bm = blockIdx.y * TBM;
    const int bn = blockIdx.x * TBN;
    const int tid = threadIdx.x;
    const int w = tid >> 5, lane = tid & 31;
    const int g = lane >> 2, t = lane & 3;
    const int wm = (w & 1) * 32;
    const int wn = (w >> 1) * 32;

    float acc[2][4][4];
    #pragma unroll
    for (int mi = 0; mi < 2; mi++)
        #pragma unroll
        for (int ni = 0; ni < 4; ni++)
            #pragma unroll
            for (int r = 0; r < 4; r++) acc[mi][ni][r] = 0.f;

    auto issue = [&](int k0, int bufi) {
        uint32_t abase = (uint32_t)__cvta_generic_to_shared(&As[bufi][0]);
        uint32_t wbase = (uint32_t)__cvta_generic_to_shared(&Ws[bufi][0]);
        #pragma unroll
        for (int i = 0; i < 2; i++) {
            int ch = tid * 2 + i;
            int r = ch >> 2, c = (ch & 3) * 4;
            cpa16(abase + (uint32_t)(r * ASL + c) * 4,
                  Ain + (size_t)(bm + r) * D_ + k0 + c);
        }
        #pragma unroll
        for (int i = 0; i < 2; i++) {
            int ch = tid * 2 + i;
            int r = ch >> 4, c = (ch & 15) * 4;
            cpa16(wbase + (uint32_t)(r * WSL + c) * 4,
                  W + (size_t)(k0 + r) * D_ + bn + c);
        }
    };

    issue(0, 0);
    asm volatile("cp.async.commit_group;");

    for (int kt = 0; kt < NKT; kt++) {
        int buf = kt & 1;
        if (kt + 1 < NKT) {
            issue((kt + 1) * TBK, buf ^ 1);
            asm volatile("cp.async.commit_group;");
            asm volatile("cp.async.wait_group 1;");
        } else {
            asm volatile("cp.async.wait_group 0;");
        }
        __syncthreads();

        const float* Ab = &As[buf][0];
        const float* Wb = &Ws[buf][0];

        #pragma unroll
        for (int kk = 0; kk < 2; kk++) {
            const int kb = kk * 8;
            float a[2][4];
            #pragma unroll
            for (int mi = 0; mi < 2; mi++) {
                const float* ar0 = Ab + (wm + mi * 16 + g) * ASL + kb;
                const float* ar1 = Ab + (wm + mi * 16 + g + 8) * ASL + kb;
                a[mi][0] = f2tf32(ar0[t]);
                a[mi][1] = f2tf32(ar1[t]);
                a[mi][2] = f2tf32(ar0[t + 4]);
                a[mi][3] = f2tf32(ar1[t + 4]);
            }
            float bf[4][2];
            #pragma unroll
            for (int ni = 0; ni < 4; ni++) {
                bf[ni][0] = f2tf32(Wb[(kb + t) * WSL + wn + ni * 8 + g]);
                bf[ni][1] = f2tf32(Wb[(kb + t + 4) * WSL + wn + ni * 8 + g]);
            }
            #pragma unroll
            for (int mi = 0; mi < 2; mi++)
                #pragma unroll
                for (int ni = 0; ni < 4; ni++)
                    mma_tf32(acc[mi][ni][0], acc[mi][ni][1],
                             acc[mi][ni][2], acc[mi][ni][3],
                             a[mi][0], a[mi][1], a[mi][2], a[mi][3],
                             bf[ni][0], bf[ni][1]);
        }
        __syncthreads();
    }

    #pragma unroll
    for (int mi = 0; mi < 2; mi++) {
        int r0 = bm + wm + mi * 16 + g;
        int r1 = r0 + 8;
        #pragma unroll
        for (int ni = 0; ni < 4; ni++) {
            int col = bn + wn + ni * 8 + 2 * t;
            if (mode == 3) {
                float2 bb = *(const float2*)&bias[col];
                *(float2*)&dst[(size_t)r0 * D_ + col] =
                    make_float2(acc[mi][ni][0] + bb.x, acc[mi][ni][1] + bb.y);
                *(float2*)&dst[(size_t)r1 * D_ + col] =
                    make_float2(acc[mi][ni][2] + bb.x, acc[mi][ni][3] + bb.y);
            } else {
                float* qkv = (z == 0) ? g_Q : (z == 1) ? g_K : g_V;
                int qs = (z == 2) ? DH_ : DHP_;
                int h = col / DH_, c = col - h * DH_;
                int b0r = r0 / N_, n0r = r0 - b0r * N_;
                int b1r = r1 / N_, n1r = r1 - b1r * N_;
                size_t base0 = (((size_t)(b0r * H_ + h)) * N_ + n0r) * qs;
                size_t base1 = (((size_t)(b1r * H_ + h)) * N_ + n1r) * qs;
                if (z == 1) {
                    // K: fragment-major scatter (pair lands non-adjacent)
                    int p0 = kperm(c), p1 = kperm(c + 1);
                    qkv[base0 + p0] = f2tf32(acc[mi][ni][0]);
                    qkv[base0 + p1] = f2tf32(acc[mi][ni][1]);
                    qkv[base1 + p0] = f2tf32(acc[mi][ni][2]);
                    qkv[base1 + p1] = f2tf32(acc[mi][ni][3]);
                } else {
                    *(float2*)&qkv[base0 + c] =
                        make_float2(f2tf32(acc[mi][ni][0] * scale),
                                    f2tf32(acc[mi][ni][1] * scale));
                    *(float2*)&qkv[base1 + c] =
                        make_float2(f2tf32(acc[mi][ni][2] * scale),
                                    f2tf32(acc[mi][ni][3] * scale));
                }
            }
        }
    }
}

// ---------------- tensor-core flash attention (tf32 mma, mask-in-MMA) ------
// K fragment-major: B-fragments load as 3x LDS.128 per key row.
#define KT 32
#define KS 48          // dense fragment-major rows; starts 16g+12t tile banks
#define VS 40          // V dense (rows by t: banks (8t+g) distinct)
#define PS 36
#define NT (N_ / KT)   // 96 tiles

__global__ __launch_bounds__(128) void attn_kernel() {
    __shared__ float Ksm[2][KT * KS];
    __shared__ float Vsm[2][KT * VS];
    __shared__ float Psm[4][32 * PS];

    const int bh = blockIdx.y;
    const int b  = bh >> 3;
    const int h  = bh & 7;
    const int tid  = threadIdx.x;
    const int w    = tid >> 5;
    const int lane = tid & 31;
    const int g = lane >> 2;
    const int t = lane & 3;
    const int q0 = blockIdx.x * 128 + w * 32;

    const float* Qb = g_Q + (size_t)bh * N_ * DHP_;
    const float* Kb = g_K + (size_t)bh * N_ * DHP_;
    const float* Vb = g_V + (size_t)bh * N_ * DH_;

    float aq[2][6][4];
    #pragma unroll
    for (int mi = 0; mi < 2; mi++) {
        const float* qr0 = Qb + (size_t)(q0 + mi * 16 + g) * DHP_;
        const float* qr1 = Qb + (size_t)(q0 + mi * 16 + g + 8) * DHP_;
        #pragma unroll
        for (int ks = 0; ks < 6; ks++) {
            aq[mi][ks][0] = qr0[8 * ks + t];
            aq[mi][ks][1] = qr1[8 * ks + t];
            aq[mi][ks][2] = qr0[8 * ks + t + 4];
            aq[mi][ks][3] = qr1[8 * ks + t + 4];
        }
    }

    float o[2][5][4];
    float l[2][2];
    #pragma unroll
    for (int mi = 0; mi < 2; mi++) {
        l[mi][0] = 0.f; l[mi][1] = 0.f;
        #pragma unroll
        for (int i = 0; i < 5; i++)
            #pragma unroll
            for (int r = 0; r < 4; r++) o[mi][i][r] = 0.f;
    }

    auto issue = [&](int tile, int bufi) {
        const float4* kg = (const float4*)(Kb + (size_t)tile * KT * DHP_);
        const float4* vg = (const float4*)(Vb + (size_t)tile * KT * DH_);
        uint32_t kdst = (uint32_t)__cvta_generic_to_shared(&Ksm[bufi][0]);
        uint32_t vdst = (uint32_t)__cvta_generic_to_shared(&Vsm[bufi][0]);
        #pragma unroll
        for (int i = 0; i < 3; i++) {
            int c = tid + i * 128;                 // 0..383: K tile is dense
            cpa16(kdst + (uint32_t)c * 16, kg + c);
            if (c < 320)
                cpa16(vdst + (uint32_t)c * 16, vg + c);   // dense: VS == DH_
        }
    };

    issue(0, 0);
    asm volatile("cp.async.commit_group;");

    for (int tile = 0; tile < NT; tile++) {
        int buf = tile & 1;
        if (tile + 1 < NT) {
            issue(tile + 1, buf ^ 1);
            asm volatile("cp.async.commit_group;");
            asm volatile("cp.async.wait_group 1;");
        } else {
            asm volatile("cp.async.wait_group 0;");
        }
        __syncthreads();

        const float* Kt = &Ksm[buf][0];
        const float* Vt = &Vsm[buf][0];
        float* Pw = &Psm[w][0];

        // ---- scores: S[32,32] = Qp @ Kp^T (mask included); vector K frags
        #pragma unroll
        for (int nb = 0; nb < 4; nb++) {
            const float* krow = Kt + (nb * 8 + g) * KS + t * 12;
            float4 f0 = *(const float4*)(krow);
            float4 f1 = *(const float4*)(krow + 4);
            float4 f2 = *(const float4*)(krow + 8);
            float bfr[6][2] = {{f0.x, f0.y}, {f0.z, f0.w},
                               {f1.x, f1.y}, {f1.z, f1.w},
                               {f2.x, f2.y}, {f2.z, f2.w}};
            #pragma unroll
            for (int mi = 0; mi < 2; mi++) {
                float d0 = 0.f, d1 = 0.f, d2 = 0.f, d3 = 0.f;
                #pragma unroll
                for (int ks = 0; ks < 6; ks++)
                    mma_tf32(d0, d1, d2, d3,
                             aq[mi][ks][0], aq[mi][ks][1],
                             aq[mi][ks][2], aq[mi][ks][3],
                             bfr[ks][0], bfr[ks][1]);
                float p0 = __expf(d0);
                float p1 = __expf(d1);
                float p2 = __expf(d2);
                float p3 = __expf(d3);
                l[mi][0] += p0 + p1;
                l[mi][1] += p2 + p3;
                *(float2*)&Pw[(mi * 16 + g) * PS + nb * 8 + 2 * t] =
                    make_float2(p0, p1);
                *(float2*)&Pw[(mi * 16 + g + 8) * PS + nb * 8 + 2 * t] =
                    make_float2(p2, p3);
            }
        }
        __syncwarp();

        // ---- O += P @ V; V fragments reused across mi
        #pragma unroll
        for (int kb = 0; kb < 4; kb++) {
            float bv[5][2];
            const float* vr0 = Vt + (kb * 8 + t) * VS;
            const float* vr1 = Vt + (kb * 8 + t + 4) * VS;
            #pragma unroll
            for (int nbo = 0; nbo < 5; nbo++) {
                bv[nbo][0] = vr0[nbo * 8 + g];
                bv[nbo][1] = vr1[nbo * 8 + g];
            }
            #pragma unroll
            for (int mi = 0; mi < 2; mi++) {
                float a0 = Pw[(mi * 16 + g) * PS + kb * 8 + t];
                float a1 = Pw[(mi * 16 + g + 8) * PS + kb * 8 + t];
                float a2 = Pw[(mi * 16 + g) * PS + kb * 8 + t + 4];
                float a3 = Pw[(mi * 16 + g + 8) * PS + kb * 8 + t + 4];
                #pragma unroll
                for (int nbo = 0; nbo < 5; nbo++)
                    mma_tf32(o[mi][nbo][0], o[mi][nbo][1],
                             o[mi][nbo][2], o[mi][nbo][3],
                             a0, a1, a2, a3, bv[nbo][0], bv[nbo][1]);
            }
        }
        __syncwarp();
        __syncthreads();
    }

    // ---- reduce row sums across quads, normalize, write
    #pragma unroll
    for (int mi = 0; mi < 2; mi++) {
        l[mi][0] += __shfl_xor_sync(0xffffffffu, l[mi][0], 1);
        l[mi][0] += __shfl_xor_sync(0xffffffffu, l[mi][0], 2);
        l[mi][1] += __shfl_xor_sync(0xffffffffu, l[mi][1], 1);
        l[mi][1] += __shfl_xor_sync(0xffffffffu, l[mi][1], 2);

        float inv0, inv1;
        if (l[mi][0] > 1e-15f) {
            inv0 = 1.f / l[mi][0];
        } else {
            #pragma unroll
            for (int nbo = 0; nbo < 5; nbo++) { o[mi][nbo][0] = 0.f; o[mi][nbo][1] = 0.f; }
            for (int j = 0; j < N_; j++) {
                const float* vr = Vb + (size_t)j * DH_;
                #pragma unroll
                for (int nbo = 0; nbo < 5; nbo++) {
                    o[mi][nbo][0] += vr[nbo * 8 + 2 * t];
                    o[mi][nbo][1] += vr[nbo * 8 + 2 * t + 1];
                }
            }
            inv0 = 1.f / (float)N_;
        }
        if (l[mi][1] > 1e-15f) {
            inv1 = 1.f / l[mi][1];
        } else {
            #pragma unroll
            for (int nbo = 0; nbo < 5; nbo++) { o[mi][nbo][2] = 0.f; o[mi][nbo][3] = 0.f; }
            for (int j = 0; j < N_; j++) {
                const float* vr = Vb + (size_t)j * DH_;
                #pragma unroll
                for (int nbo = 0; nbo < 5; nbo++) {
                    o[mi][nbo][2] += vr[nbo * 8 + 2 * t];
                    o[mi][nbo][3] += vr[nbo * 8 + 2 * t + 1];
                }
            }
            inv1 = 1.f / (float)N_;
        }

        float* O0 = g_O + (size_t)(b * N_ + q0 + mi * 16 + g) * D_ + h * DH_;
        float* O1 = g_O + (size_t)(b * N_ + q0 + mi * 16 + g + 8) * D_ + h * DH_;
        #pragma unroll
        for (int nbo = 0; nbo < 5; nbo++) {
            *(float2*)&O0[nbo * 8 + 2 * t] =
                make_float2(o[mi][nbo][0] * inv0, o[mi][nbo][1] * inv0);
            *(float2*)&O1[nbo * 8 + 2 * t] =
                make_float2(o[mi][nbo][2] * inv1, o[mi][nbo][3] * inv1);
        }
    }
}

// ---------------- launch ----------------
extern "C" void kernel_launch(void* const* d_in, const int* in_sizes, int n_in,
                              void* d_out, int out_size) {
    (void)in_sizes; (void)n_in; (void)out_size;
    const float* x     = (const float*)d_in[0];
    const float* ctx   = (const float*)d_in[1];
    const float* mask1 = (const float*)d_in[2];
    const float* mask2 = (const float*)d_in[3];
    const float* Wq    = (const float*)d_in[4];
    const float* Wk    = (const float*)d_in[5];
    const float* Wv    = (const float*)d_in[6];
    const float* Wo    = (const float*)d_in[7];
    const float* bo    = (const float*)d_in[8];
    float* out = (float*)d_out;

    dim3 gqkv(D_ / TBN, (B_ * N_) / TBM, 3);   // (5, 96, 3)
    dim3 gout(D_ / TBN, (B_ * N_) / TBM, 1);

    mask_kernel<<<(B_ * N_ + 255) / 256, 256>>>(mask1, mask2);
    gemm_tf32_kernel<<<gqkv, 128>>>(x, ctx, Wq, Wk, Wv, nullptr, 0, nullptr);
    attn_kernel<<<dim3(N_ / 128, BH_), 128>>>();
    gemm_tf32_kernel<<<gout, 128>>>(nullptr, nullptr, Wo, nullptr, nullptr, bo, 3, out);
}